// round 15
// baseline (speedup 1.0000x reference)
#include <cuda_runtime.h>
#include <cuda_fp16.h>
#include <cstdint>

#define B_ROWS 16384
#define K_DIM  4096
#define N_DIM  4096

// -------- scratch (allocation-free rule: __device__ globals) --------
__device__ __half g_xh[(size_t)B_ROWS * K_DIM];   // x in fp16 (rn)
__device__ __half g_Wth[(size_t)N_DIM * K_DIM];   // W^T: [N][K], fp16 (rn)
__device__ float  g_inv[B_ROWS];                  // 1/(||x_row|| + 1e-5)

__device__ __forceinline__ uint32_t smem_u32(const void* p) {
    uint32_t a;
    asm("{ .reg .u64 t; cvta.to.shared.u64 t, %1; cvt.u32.u64 %0, t; }" : "=r"(a) : "l"(p));
    return a;
}

// ==================== kernel 1: fused prep ====================
// blocks [0, B_ROWS): row norms + fp16 convert of x
// blocks [B_ROWS, B_ROWS + 16384): W transpose -> Wth fp16 (32x32 tiles)
__global__ void prep_kernel(const float* __restrict__ x, const float* __restrict__ W) {
    __shared__ float sh[32 * 33];
    int tid = threadIdx.x;

    if (blockIdx.x < B_ROWS) {
        int row = blockIdx.x;
        const float4* xr = (const float4*)(x + (size_t)row * K_DIM);
        uint2* xh = (uint2*)(g_xh + (size_t)row * K_DIM);
        float s = 0.f;
#pragma unroll
        for (int i = 0; i < 4; i++) {
            float4 v = xr[tid + i * 256];
            s += v.x * v.x + v.y * v.y + v.z * v.z + v.w * v.w;
            __half2 h0 = __floats2half2_rn(v.x, v.y);
            __half2 h1 = __floats2half2_rn(v.z, v.w);
            uint2 u;
            u.x = *reinterpret_cast<uint32_t*>(&h0);
            u.y = *reinterpret_cast<uint32_t*>(&h1);
            xh[tid + i * 256] = u;
        }
#pragma unroll
        for (int o = 16; o; o >>= 1) s += __shfl_xor_sync(0xffffffffu, s, o);
        if ((tid & 31) == 0) sh[tid >> 5] = s;
        __syncthreads();
        if (tid == 0) {
            float t = 0.f;
#pragma unroll
            for (int i = 0; i < 8; i++) t += sh[i];
            g_inv[row] = 1.0f / (sqrtf(t) + 1e-5f);
        }
    } else {
        int bx = blockIdx.x - B_ROWS;          // 0..16383
        int n0 = (bx & 127) << 5;              // 128 n-tiles
        int k0 = (bx >> 7) << 5;               // 128 k-tiles
        int tx = tid & 31, ty = tid >> 5;      // 32 x 8
#pragma unroll
        for (int i = 0; i < 32; i += 8)
            sh[(ty + i) * 33 + tx] = W[(size_t)(k0 + ty + i) * N_DIM + n0 + tx];
        __syncthreads();
#pragma unroll
        for (int i = 0; i < 32; i += 8)
            g_Wth[(size_t)(n0 + ty + i) * K_DIM + k0 + tx] =
                __float2half_rn(sh[tx * 33 + ty + i]);
    }
}

// ==================== kernel 2: persistent fp16 mma.sync GEMM ====================
// Persistent CTAs (grid 304 = 2/SM), each walks tiles bid, bid+304, ...
// CTA tile 128x128x64, 4 warps (64x64), 3-stage cp.async pipeline whose buffer
// index rotates CONTINUOUSLY across tile boundaries -> only the first tile pays
// a cold fill; next tile's stages prefetch during the previous tile's last iters.
static constexpr int BM = 128, BN = 128, BK = 64;
static constexpr int STAGES = 3;
static constexpr int ATILE_B = BM * BK * 2;           // 16 KB
static constexpr int STAGE_B = 2 * ATILE_B;           // A + B = 32 KB
static constexpr int SMEM_B  = STAGES * STAGE_B;      // 96 KB
static constexpr int NK = K_DIM / BK;                 // 64
static constexpr int NTILES = (B_ROWS / BM) * (N_DIM / BN);   // 4096
static constexpr int GRID   = 304;                    // 2 CTAs/SM on 152 SMs

__device__ __forceinline__ void stage_loads(int m0, int n0, int ks,
                                            uint32_t sbase, int tid) {
    int c  = tid & 7;        // 16B chunk within 128B row
    int r0 = tid >> 3;       // 0..15
    size_t koff = (size_t)ks * BK + (c << 3);   // 8 halves = 16B per chunk
#pragma unroll
    for (int p = 0; p < 8; p++) {
        int row = r0 + (p << 4);
        const __half* src = g_xh + (size_t)(m0 + row) * K_DIM + koff;
        uint32_t dst = sbase + row * 128 + ((c ^ (row & 7)) << 4);
        asm volatile("cp.async.cg.shared.global [%0], [%1], 16;" :: "r"(dst), "l"(src));
    }
#pragma unroll
    for (int p = 0; p < 8; p++) {
        int row = r0 + (p << 4);
        const __half* src = g_Wth + (size_t)(n0 + row) * K_DIM + koff;
        uint32_t dst = sbase + ATILE_B + row * 128 + ((c ^ (row & 7)) << 4);
        asm volatile("cp.async.cg.shared.global [%0], [%1], 16;" :: "r"(dst), "l"(src));
    }
}

__global__ void __launch_bounds__(128, 2)
gemm_kernel(const float* __restrict__ bias, float* __restrict__ out) {
    extern __shared__ char smem_raw[];
    uint32_t sbase = smem_u32(smem_raw);

    int tid  = threadIdx.x;
    int w    = tid >> 5, lane = tid & 31;

    int wm = (w & 1) << 6;                 // warp M origin (0/64)
    int wn = (w >> 1) << 6;                // warp N origin (0/64)

    int l7 = lane & 7;
    int rowA = wm + l7 + (((lane >> 3) & 1) << 3);
    int khA  = lane >> 4;
    int swA  = rowA & 7;
    uint32_t aBase = (uint32_t)(rowA * 128);
    int rowB = wn + l7 + (((lane >> 4) & 1) << 3);
    int khB  = (lane >> 3) & 1;
    int swB  = rowB & 7;
    uint32_t bBase = (uint32_t)(ATILE_B + rowB * 128);

    // prologue: first tile's stages 0,1  (n fastest within tile index)
    {
        int t0 = blockIdx.x;
        int m0 = (t0 >> 5) << 7, n0 = (t0 & 31) << 7;
        stage_loads(m0, n0, 0, sbase, tid);
        asm volatile("cp.async.commit_group;" ::: "memory");
        stage_loads(m0, n0, 1, sbase + STAGE_B, tid);
        asm volatile("cp.async.commit_group;" ::: "memory");
    }

    int buf = 0;   // rotating stage buffer index, continuous across tiles

#pragma unroll 1
    for (int tile = blockIdx.x; tile < NTILES; tile += GRID) {
        int n0 = (tile & 31) << 7;
        int m0 = (tile >> 5) << 7;

        float acc[4][8][4];
#pragma unroll
        for (int i = 0; i < 4; i++)
#pragma unroll
            for (int j = 0; j < 8; j++)
#pragma unroll
                for (int r = 0; r < 4; r++) acc[i][j][r] = 0.f;

#pragma unroll 1
        for (int ks = 0; ks < NK; ks++) {
            asm volatile("cp.async.wait_group 1;" ::: "memory");
            __syncthreads();

            uint32_t sb = sbase + buf * STAGE_B;
#pragma unroll
            for (int kk = 0; kk < 4; kk++) {           // four k16 steps per BK=64
                uint32_t a[4][4], b[8][2];
                uint32_t offA = (uint32_t)((((kk << 1) | khA) ^ swA) << 4);
#pragma unroll
                for (int i = 0; i < 4; i++) {
                    uint32_t addr = sb + aBase + (i << 11) + offA;
                    asm volatile(
                        "ldmatrix.sync.aligned.m8n8.x4.shared.b16 {%0,%1,%2,%3}, [%4];"
                        : "=r"(a[i][0]), "=r"(a[i][1]), "=r"(a[i][2]), "=r"(a[i][3])
                        : "r"(addr));
                }
                uint32_t offB = (uint32_t)((((kk << 1) | khB) ^ swB) << 4);
#pragma unroll
                for (int j = 0; j < 4; j++) {
                    uint32_t addr = sb + bBase + (j << 11) + offB;
                    asm volatile(
                        "ldmatrix.sync.aligned.m8n8.x4.shared.b16 {%0,%1,%2,%3}, [%4];"
                        : "=r"(b[2 * j][0]), "=r"(b[2 * j][1]),
                          "=r"(b[2 * j + 1][0]), "=r"(b[2 * j + 1][1])
                        : "r"(addr));
                }
#pragma unroll
                for (int i = 0; i < 4; i++)
#pragma unroll
                    for (int j = 0; j < 8; j++) {
                        asm volatile(
                            "mma.sync.aligned.m16n8k16.row.col.f32.f16.f16.f32 "
                            "{%0,%1,%2,%3}, {%4,%5,%6,%7}, {%8,%9}, {%0,%1,%2,%3};"
                            : "+f"(acc[i][j][0]), "+f"(acc[i][j][1]),
                              "+f"(acc[i][j][2]), "+f"(acc[i][j][3])
                            : "r"(a[i][0]), "r"(a[i][1]), "r"(a[i][2]), "r"(a[i][3]),
                              "r"(b[j][0]), "r"(b[j][1]));
                    }
            }

            // prefetch linear-index +2 (may belong to the NEXT tile) into buffer
            // (buf+2)%3 — same safety invariant as before, now continuous across tiles.
            {
                int ksp = ks + 2, tilep = tile;
                if (ksp >= NK) { ksp -= NK; tilep += GRID; }
                if (tilep < NTILES) {
                    int m0p = (tilep >> 5) << 7, n0p = (tilep & 31) << 7;
                    int bufp = buf + 2; if (bufp >= STAGES) bufp -= STAGES;
                    stage_loads(m0p, n0p, ksp, sbase + bufp * STAGE_B, tid);
                }
                asm volatile("cp.async.commit_group;" ::: "memory");
            }
            if (++buf == STAGES) buf = 0;
        }

        // ---- epilogue: scale by inv-norm, add bias, relu, store (no stage smem) ----
        int g = lane >> 2, t4 = lane & 3;
        float2 bia[8];
#pragma unroll
        for (int j = 0; j < 8; j++)
            bia[j] = *(const float2*)(bias + n0 + wn + j * 8 + 2 * t4);

#pragma unroll
        for (int i = 0; i < 4; i++) {
            int row_lo = m0 + wm + i * 16 + g;
            int row_hi = row_lo + 8;
            float inv_lo = g_inv[row_lo];
            float inv_hi = g_inv[row_hi];
            float* out_lo = out + (size_t)row_lo * N_DIM + n0 + wn + 2 * t4;
            float* out_hi = out + (size_t)row_hi * N_DIM + n0 + wn + 2 * t4;
#pragma unroll
            for (int j = 0; j < 8; j++) {
                float2 v;
                v.x = fmaxf(fmaf(acc[i][j][0], inv_lo, bia[j].x), 0.f);
                v.y = fmaxf(fmaf(acc[i][j][1], inv_lo, bia[j].y), 0.f);
                *(float2*)(out_lo + j * 8) = v;
                v.x = fmaxf(fmaf(acc[i][j][2], inv_hi, bia[j].x), 0.f);
                v.y = fmaxf(fmaf(acc[i][j][3], inv_hi, bia[j].y), 0.f);
                *(float2*)(out_hi + j * 8) = v;
            }
        }
    }
}

// ==================== launch ====================
extern "C" void kernel_launch(void* const* d_in, const int* in_sizes, int n_in,
                              void* d_out, int out_size) {
    const float* x = (const float*)d_in[0];
    const float* W = (const float*)d_in[1];
    const float* b = (const float*)d_in[2];
    float* out = (float*)d_out;

    cudaFuncSetAttribute(gemm_kernel, cudaFuncAttributeMaxDynamicSharedMemorySize, SMEM_B);

    prep_kernel<<<B_ROWS + (K_DIM / 32) * (N_DIM / 32), 256>>>(x, W);
    gemm_kernel<<<GRID, 128, SMEM_B>>>(b, out);
}

// round 16
// speedup vs baseline: 1.0253x; 1.0253x over previous
#include <cuda_runtime.h>
#include <cuda_fp16.h>
#include <cstdint>

#define B_ROWS 16384
#define K_DIM  4096
#define N_DIM  4096

// -------- scratch (allocation-free rule: __device__ globals) --------
__device__ __half g_xh[(size_t)B_ROWS * K_DIM];   // x in fp16 (rn)
__device__ __half g_Wth[(size_t)N_DIM * K_DIM];   // W^T: [N][K], fp16 (rn)
__device__ float  g_inv[B_ROWS];                  // 1/(||x_row|| + 1e-5)

__device__ __forceinline__ uint32_t smem_u32(const void* p) {
    uint32_t a;
    asm("{ .reg .u64 t; cvta.to.shared.u64 t, %1; cvt.u32.u64 %0, t; }" : "=r"(a) : "l"(p));
    return a;
}
__device__ __forceinline__ uint32_t packh2(float lo, float hi) {
    __half2 h = __floats2half2_rn(lo, hi);
    return *reinterpret_cast<uint32_t*>(&h);
}

// ==================== kernel 1: fused prep ====================
// blocks [0, B_ROWS): row norms + fp16 convert of x (16 contiguous floats/thread,
//                     4x LDG.128 + 2x STG.128, fully coalesced)
// blocks [B_ROWS, B_ROWS + 16384): W transpose -> Wth fp16 (32x32 tiles)
__global__ void prep_kernel(const float* __restrict__ x, const float* __restrict__ W) {
    __shared__ float sh[32 * 33];
    int tid = threadIdx.x;

    if (blockIdx.x < B_ROWS) {
        int row = blockIdx.x;
        const float4* xr = (const float4*)(x + (size_t)row * K_DIM + tid * 16);
        uint4* xh = (uint4*)(g_xh + (size_t)row * K_DIM + tid * 16);
        float4 v0 = xr[0], v1 = xr[1], v2 = xr[2], v3 = xr[3];
        float s = v0.x * v0.x + v0.y * v0.y + v0.z * v0.z + v0.w * v0.w
                + v1.x * v1.x + v1.y * v1.y + v1.z * v1.z + v1.w * v1.w
                + v2.x * v2.x + v2.y * v2.y + v2.z * v2.z + v2.w * v2.w
                + v3.x * v3.x + v3.y * v3.y + v3.z * v3.z + v3.w * v3.w;
        uint4 o0, o1;
        o0.x = packh2(v0.x, v0.y); o0.y = packh2(v0.z, v0.w);
        o0.z = packh2(v1.x, v1.y); o0.w = packh2(v1.z, v1.w);
        o1.x = packh2(v2.x, v2.y); o1.y = packh2(v2.z, v2.w);
        o1.z = packh2(v3.x, v3.y); o1.w = packh2(v3.z, v3.w);
        xh[0] = o0;
        xh[1] = o1;
#pragma unroll
        for (int o = 16; o; o >>= 1) s += __shfl_xor_sync(0xffffffffu, s, o);
        if ((tid & 31) == 0) sh[tid >> 5] = s;
        __syncthreads();
        if (tid == 0) {
            float t = 0.f;
#pragma unroll
            for (int i = 0; i < 8; i++) t += sh[i];
            g_inv[row] = 1.0f / (sqrtf(t) + 1e-5f);
        }
    } else {
        int bx = blockIdx.x - B_ROWS;          // 0..16383
        int n0 = (bx & 127) << 5;              // 128 n-tiles
        int k0 = (bx >> 7) << 5;               // 128 k-tiles
        int tx = tid & 31, ty = tid >> 5;      // 32 x 8
#pragma unroll
        for (int i = 0; i < 32; i += 8)
            sh[(ty + i) * 33 + tx] = W[(size_t)(k0 + ty + i) * N_DIM + n0 + tx];
        __syncthreads();
#pragma unroll
        for (int i = 0; i < 32; i += 8)
            g_Wth[(size_t)(n0 + ty + i) * K_DIM + k0 + tx] =
                __float2half_rn(sh[tx * 33 + ty + i]);
    }
}

// ==================== kernel 2: fp16 mma.sync GEMM + fused epilogue ====================
// (R12 mainloop — verified best at 1182.1 us; do not restructure.)
// CTA 128x128x64, 4 warps (warp tile 64x64), 3-stage cp.async pipeline (96 KB),
// single __syncthreads per mainloop iteration (prefetch-after-compute).
static constexpr int BM = 128, BN = 128, BK = 64;
static constexpr int STAGES = 3;
static constexpr int ATILE_B = BM * BK * 2;           // 16 KB
static constexpr int STAGE_B = 2 * ATILE_B;           // A + B = 32 KB
static constexpr int SMEM_B  = STAGES * STAGE_B;      // 96 KB
static constexpr int NK = K_DIM / BK;                 // 64

__device__ __forceinline__ void stage_loads(int m0, int n0, int ks,
                                            uint32_t sbase, int tid) {
    int c  = tid & 7;        // 16B chunk within 128B row
    int r0 = tid >> 3;       // 0..15
    size_t koff = (size_t)ks * BK + (c << 3);   // 8 halves = 16B per chunk
#pragma unroll
    for (int p = 0; p < 8; p++) {
        int row = r0 + (p << 4);
        const __half* src = g_xh + (size_t)(m0 + row) * K_DIM + koff;
        uint32_t dst = sbase + row * 128 + ((c ^ (row & 7)) << 4);
        asm volatile("cp.async.cg.shared.global [%0], [%1], 16;" :: "r"(dst), "l"(src));
    }
#pragma unroll
    for (int p = 0; p < 8; p++) {
        int row = r0 + (p << 4);
        const __half* src = g_Wth + (size_t)(n0 + row) * K_DIM + koff;
        uint32_t dst = sbase + ATILE_B + row * 128 + ((c ^ (row & 7)) << 4);
        asm volatile("cp.async.cg.shared.global [%0], [%1], 16;" :: "r"(dst), "l"(src));
    }
}

__global__ void __launch_bounds__(128, 2)
gemm_kernel(const float* __restrict__ bias, float* __restrict__ out) {
    extern __shared__ char smem_raw[];
    uint32_t sbase = smem_u32(smem_raw);

    int tid  = threadIdx.x;
    int w    = tid >> 5, lane = tid & 31;
    int bid  = blockIdx.x;
    int n0   = (bid & 31) << 7;            // n fastest: wave shares the W panel in L2
    int m0   = (bid >> 5) << 7;

    int wm = (w & 1) << 6;                 // warp M origin (0/64)
    int wn = (w >> 1) << 6;                // warp N origin (0/64)

    int l7 = lane & 7;
    int rowA = wm + l7 + (((lane >> 3) & 1) << 3);
    int khA  = lane >> 4;
    int swA  = rowA & 7;
    uint32_t aBase = (uint32_t)(rowA * 128);
    int rowB = wn + l7 + (((lane >> 4) & 1) << 3);
    int khB  = (lane >> 3) & 1;
    int swB  = rowB & 7;
    uint32_t bBase = (uint32_t)(ATILE_B + rowB * 128);

    float acc[4][8][4];
#pragma unroll
    for (int i = 0; i < 4; i++)
#pragma unroll
        for (int j = 0; j < 8; j++)
#pragma unroll
            for (int r = 0; r < 4; r++) acc[i][j][r] = 0.f;

    // prologue: stages 0,1
    stage_loads(m0, n0, 0, sbase, tid);
    asm volatile("cp.async.commit_group;" ::: "memory");
    stage_loads(m0, n0, 1, sbase + STAGE_B, tid);
    asm volatile("cp.async.commit_group;" ::: "memory");

#pragma unroll 1
    for (int ks = 0; ks < NK; ks++) {
        asm volatile("cp.async.wait_group 1;" ::: "memory");
        __syncthreads();

        uint32_t sb = sbase + (ks % STAGES) * STAGE_B;
#pragma unroll
        for (int kk = 0; kk < 4; kk++) {               // four k16 steps per BK=64
            uint32_t a[4][4], b[8][2];
            uint32_t offA = (uint32_t)((((kk << 1) | khA) ^ swA) << 4);
#pragma unroll
            for (int i = 0; i < 4; i++) {
                uint32_t addr = sb + aBase + (i << 11) + offA;   // 16 rows * 128B = 2KB
                asm volatile(
                    "ldmatrix.sync.aligned.m8n8.x4.shared.b16 {%0,%1,%2,%3}, [%4];"
                    : "=r"(a[i][0]), "=r"(a[i][1]), "=r"(a[i][2]), "=r"(a[i][3])
                    : "r"(addr));
            }
            uint32_t offB = (uint32_t)((((kk << 1) | khB) ^ swB) << 4);
#pragma unroll
            for (int j = 0; j < 4; j++) {
                uint32_t addr = sb + bBase + (j << 11) + offB;
                asm volatile(
                    "ldmatrix.sync.aligned.m8n8.x4.shared.b16 {%0,%1,%2,%3}, [%4];"
                    : "=r"(b[2 * j][0]), "=r"(b[2 * j][1]),
                      "=r"(b[2 * j + 1][0]), "=r"(b[2 * j + 1][1])
                    : "r"(addr));
            }
#pragma unroll
            for (int i = 0; i < 4; i++)
#pragma unroll
                for (int j = 0; j < 8; j++) {
                    asm volatile(
                        "mma.sync.aligned.m16n8k16.row.col.f32.f16.f16.f32 "
                        "{%0,%1,%2,%3}, {%4,%5,%6,%7}, {%8,%9}, {%0,%1,%2,%3};"
                        : "+f"(acc[i][j][0]), "+f"(acc[i][j][1]),
                          "+f"(acc[i][j][2]), "+f"(acc[i][j][3])
                        : "r"(a[i][0]), "r"(a[i][1]), "r"(a[i][2]), "r"(a[i][3]),
                          "r"(b[j][0]), "r"(b[j][1]));
                }
        }

        // prefetch stage ks+2 AFTER compute: writes buffer (ks+2)%3 != ks%3; after the
        // top-of-iter sync no warp can still be reading iter ks-1's buffer (= (ks+2)%3).
        if (ks + 2 < NK)
            stage_loads(m0, n0, ks + 2,
                        sbase + ((ks + 2) % STAGES) * STAGE_B, tid);
        asm volatile("cp.async.commit_group;" ::: "memory");
    }

    // ---- epilogue: scale by inv-norm, add bias, relu, store ----
    int g = lane >> 2, t4 = lane & 3;
    float2 bia[8];
#pragma unroll
    for (int j = 0; j < 8; j++)
        bia[j] = *(const float2*)(bias + n0 + wn + j * 8 + 2 * t4);

#pragma unroll
    for (int i = 0; i < 4; i++) {
        int row_lo = m0 + wm + i * 16 + g;
        int row_hi = row_lo + 8;
        float inv_lo = g_inv[row_lo];
        float inv_hi = g_inv[row_hi];
        float* out_lo = out + (size_t)row_lo * N_DIM + n0 + wn + 2 * t4;
        float* out_hi = out + (size_t)row_hi * N_DIM + n0 + wn + 2 * t4;
#pragma unroll
        for (int j = 0; j < 8; j++) {
            float2 v;
            v.x = fmaxf(fmaf(acc[i][j][0], inv_lo, bia[j].x), 0.f);
            v.y = fmaxf(fmaf(acc[i][j][1], inv_lo, bia[j].y), 0.f);
            *(float2*)(out_lo + j * 8) = v;
            v.x = fmaxf(fmaf(acc[i][j][2], inv_hi, bia[j].x), 0.f);
            v.y = fmaxf(fmaf(acc[i][j][3], inv_hi, bia[j].y), 0.f);
            *(float2*)(out_hi + j * 8) = v;
        }
    }
}

// ==================== launch ====================
extern "C" void kernel_launch(void* const* d_in, const int* in_sizes, int n_in,
                              void* d_out, int out_size) {
    const float* x = (const float*)d_in[0];
    const float* W = (const float*)d_in[1];
    const float* b = (const float*)d_in[2];
    float* out = (float*)d_out;

    cudaFuncSetAttribute(gemm_kernel, cudaFuncAttributeMaxDynamicSharedMemorySize, SMEM_B);

    prep_kernel<<<B_ROWS + (K_DIM / 32) * (N_DIM / 32), 256>>>(x, W);
    gemm_kernel<<<(B_ROWS / BM) * (N_DIM / BN), 128, SMEM_B>>>(b, out);
}

// round 17
// speedup vs baseline: 1.0375x; 1.0119x over previous
#include <cuda_runtime.h>
#include <cuda_fp16.h>
#include <cstdint>

#define B_ROWS 16384
#define K_DIM  4096
#define N_DIM  4096

// -------- scratch (allocation-free rule: __device__ globals) --------
__device__ __half g_xh[(size_t)B_ROWS * K_DIM];   // x in fp16 (rn)
__device__ __half g_Wth[(size_t)N_DIM * K_DIM];   // W^T: [N][K], fp16 (rn)
__device__ float  g_inv[B_ROWS];                  // 1/(||x_row|| + 1e-5)

__device__ __forceinline__ uint32_t smem_u32(const void* p) {
    uint32_t a;
    asm("{ .reg .u64 t; cvta.to.shared.u64 t, %1; cvt.u32.u64 %0, t; }" : "=r"(a) : "l"(p));
    return a;
}
__device__ __forceinline__ uint32_t packh2(float lo, float hi) {
    __half2 h = __floats2half2_rn(lo, hi);
    return *reinterpret_cast<uint32_t*>(&h);
}

// ==================== kernel 1: fused prep ====================
// blocks [0, B_ROWS): row norms + fp16 convert of x (16 contiguous floats/thread)
// blocks [B_ROWS, B_ROWS + 16384): W transpose -> Wth fp16 (32x32 tiles)
__global__ void prep_kernel(const float* __restrict__ x, const float* __restrict__ W) {
    __shared__ float sh[32 * 33];
    int tid = threadIdx.x;

    if (blockIdx.x < B_ROWS) {
        int row = blockIdx.x;
        const float4* xr = (const float4*)(x + (size_t)row * K_DIM + tid * 16);
        uint4* xh = (uint4*)(g_xh + (size_t)row * K_DIM + tid * 16);
        float4 v0 = xr[0], v1 = xr[1], v2 = xr[2], v3 = xr[3];
        float s = v0.x * v0.x + v0.y * v0.y + v0.z * v0.z + v0.w * v0.w
                + v1.x * v1.x + v1.y * v1.y + v1.z * v1.z + v1.w * v1.w
                + v2.x * v2.x + v2.y * v2.y + v2.z * v2.z + v2.w * v2.w
                + v3.x * v3.x + v3.y * v3.y + v3.z * v3.z + v3.w * v3.w;
        uint4 o0, o1;
        o0.x = packh2(v0.x, v0.y); o0.y = packh2(v0.z, v0.w);
        o0.z = packh2(v1.x, v1.y); o0.w = packh2(v1.z, v1.w);
        o1.x = packh2(v2.x, v2.y); o1.y = packh2(v2.z, v2.w);
        o1.z = packh2(v3.x, v3.y); o1.w = packh2(v3.z, v3.w);
        xh[0] = o0;
        xh[1] = o1;
#pragma unroll
        for (int o = 16; o; o >>= 1) s += __shfl_xor_sync(0xffffffffu, s, o);
        if ((tid & 31) == 0) sh[tid >> 5] = s;
        __syncthreads();
        if (tid == 0) {
            float t = 0.f;
#pragma unroll
            for (int i = 0; i < 8; i++) t += sh[i];
            g_inv[row] = 1.0f / (sqrtf(t) + 1e-5f);
        }
    } else {
        int bx = blockIdx.x - B_ROWS;          // 0..16383
        int n0 = (bx & 127) << 5;              // 128 n-tiles
        int k0 = (bx >> 7) << 5;               // 128 k-tiles
        int tx = tid & 31, ty = tid >> 5;      // 32 x 8
#pragma unroll
        for (int i = 0; i < 32; i += 8)
            sh[(ty + i) * 33 + tx] = W[(size_t)(k0 + ty + i) * N_DIM + n0 + tx];
        __syncthreads();
#pragma unroll
        for (int i = 0; i < 32; i += 8)
            g_Wth[(size_t)(n0 + ty + i) * K_DIM + k0 + tx] =
                __float2half_rn(sh[tx * 33 + ty + i]);
    }
}

// ==================== kernel 2: fp16 mma.sync GEMM + fused epilogue ====================
// (R12/R16 mainloop — verified best; do not restructure.)
// CTA 128x128x64, 4 warps (warp tile 64x64), 3-stage cp.async pipeline (96 KB),
// single __syncthreads per mainloop iteration (prefetch-after-compute).
// NEW: odd CTAs sleep ~400ns at entry to anti-phase co-resident CTA pairs so one
// CTA's barrier window overlaps the other's MMA block on every SMSP.
static constexpr int BM = 128, BN = 128, BK = 64;
static constexpr int STAGES = 3;
static constexpr int ATILE_B = BM * BK * 2;           // 16 KB
static constexpr int STAGE_B = 2 * ATILE_B;           // A + B = 32 KB
static constexpr int SMEM_B  = STAGES * STAGE_B;      // 96 KB
static constexpr int NK = K_DIM / BK;                 // 64

__device__ __forceinline__ void stage_loads(int m0, int n0, int ks,
                                            uint32_t sbase, int tid) {
    int c  = tid & 7;        // 16B chunk within 128B row
    int r0 = tid >> 3;       // 0..15
    size_t koff = (size_t)ks * BK + (c << 3);   // 8 halves = 16B per chunk
#pragma unroll
    for (int p = 0; p < 8; p++) {
        int row = r0 + (p << 4);
        const __half* src = g_xh + (size_t)(m0 + row) * K_DIM + koff;
        uint32_t dst = sbase + row * 128 + ((c ^ (row & 7)) << 4);
        asm volatile("cp.async.cg.shared.global [%0], [%1], 16;" :: "r"(dst), "l"(src));
    }
#pragma unroll
    for (int p = 0; p < 8; p++) {
        int row = r0 + (p << 4);
        const __half* src = g_Wth + (size_t)(n0 + row) * K_DIM + koff;
        uint32_t dst = sbase + ATILE_B + row * 128 + ((c ^ (row & 7)) << 4);
        asm volatile("cp.async.cg.shared.global [%0], [%1], 16;" :: "r"(dst), "l"(src));
    }
}

__global__ void __launch_bounds__(128, 2)
gemm_kernel(const float* __restrict__ bias, float* __restrict__ out) {
    extern __shared__ char smem_raw[];
    uint32_t sbase = smem_u32(smem_raw);

    int tid  = threadIdx.x;
    int w    = tid >> 5, lane = tid & 31;
    int bid  = blockIdx.x;
    int n0   = (bid & 31) << 7;            // n fastest: wave shares the W panel in L2
    int m0   = (bid >> 5) << 7;

    // Anti-phase co-resident CTA pairs (adjacent bids land on the same SM):
    // ~half an iteration (~400 ns) so the two CTAs' barrier windows interleave.
    if (bid & 1) __nanosleep(400);

    int wm = (w & 1) << 6;                 // warp M origin (0/64)
    int wn = (w >> 1) << 6;                // warp N origin (0/64)

    int l7 = lane & 7;
    int rowA = wm + l7 + (((lane >> 3) & 1) << 3);
    int khA  = lane >> 4;
    int swA  = rowA & 7;
    uint32_t aBase = (uint32_t)(rowA * 128);
    int rowB = wn + l7 + (((lane >> 4) & 1) << 3);
    int khB  = (lane >> 3) & 1;
    int swB  = rowB & 7;
    uint32_t bBase = (uint32_t)(ATILE_B + rowB * 128);

    float acc[4][8][4];
#pragma unroll
    for (int i = 0; i < 4; i++)
#pragma unroll
        for (int j = 0; j < 8; j++)
#pragma unroll
            for (int r = 0; r < 4; r++) acc[i][j][r] = 0.f;

    // prologue: stages 0,1
    stage_loads(m0, n0, 0, sbase, tid);
    asm volatile("cp.async.commit_group;" ::: "memory");
    stage_loads(m0, n0, 1, sbase + STAGE_B, tid);
    asm volatile("cp.async.commit_group;" ::: "memory");

#pragma unroll 1
    for (int ks = 0; ks < NK; ks++) {
        asm volatile("cp.async.wait_group 1;" ::: "memory");
        __syncthreads();

        uint32_t sb = sbase + (ks % STAGES) * STAGE_B;
#pragma unroll
        for (int kk = 0; kk < 4; kk++) {               // four k16 steps per BK=64
            uint32_t a[4][4], b[8][2];
            uint32_t offA = (uint32_t)((((kk << 1) | khA) ^ swA) << 4);
#pragma unroll
            for (int i = 0; i < 4; i++) {
                uint32_t addr = sb + aBase + (i << 11) + offA;   // 16 rows * 128B = 2KB
                asm volatile(
                    "ldmatrix.sync.aligned.m8n8.x4.shared.b16 {%0,%1,%2,%3}, [%4];"
                    : "=r"(a[i][0]), "=r"(a[i][1]), "=r"(a[i][2]), "=r"(a[i][3])
                    : "r"(addr));
            }
            uint32_t offB = (uint32_t)((((kk << 1) | khB) ^ swB) << 4);
#pragma unroll
            for (int j = 0; j < 4; j++) {
                uint32_t addr = sb + bBase + (j << 11) + offB;
                asm volatile(
                    "ldmatrix.sync.aligned.m8n8.x4.shared.b16 {%0,%1,%2,%3}, [%4];"
                    : "=r"(b[2 * j][0]), "=r"(b[2 * j][1]),
                      "=r"(b[2 * j + 1][0]), "=r"(b[2 * j + 1][1])
                    : "r"(addr));
            }
#pragma unroll
            for (int i = 0; i < 4; i++)
#pragma unroll
                for (int j = 0; j < 8; j++) {
                    asm volatile(
                        "mma.sync.aligned.m16n8k16.row.col.f32.f16.f16.f32 "
                        "{%0,%1,%2,%3}, {%4,%5,%6,%7}, {%8,%9}, {%0,%1,%2,%3};"
                        : "+f"(acc[i][j][0]), "+f"(acc[i][j][1]),
                          "+f"(acc[i][j][2]), "+f"(acc[i][j][3])
                        : "r"(a[i][0]), "r"(a[i][1]), "r"(a[i][2]), "r"(a[i][3]),
                          "r"(b[j][0]), "r"(b[j][1]));
                }
        }

        // prefetch stage ks+2 AFTER compute: writes buffer (ks+2)%3 != ks%3; after the
        // top-of-iter sync no warp can still be reading iter ks-1's buffer (= (ks+2)%3).
        if (ks + 2 < NK)
            stage_loads(m0, n0, ks + 2,
                        sbase + ((ks + 2) % STAGES) * STAGE_B, tid);
        asm volatile("cp.async.commit_group;" ::: "memory");
    }

    // ---- epilogue: scale by inv-norm, add bias, relu, store ----
    int g = lane >> 2, t4 = lane & 3;
    float2 bia[8];
#pragma unroll
    for (int j = 0; j < 8; j++)
        bia[j] = *(const float2*)(bias + n0 + wn + j * 8 + 2 * t4);

#pragma unroll
    for (int i = 0; i < 4; i++) {
        int row_lo = m0 + wm + i * 16 + g;
        int row_hi = row_lo + 8;
        float inv_lo = g_inv[row_lo];
        float inv_hi = g_inv[row_hi];
        float* out_lo = out + (size_t)row_lo * N_DIM + n0 + wn + 2 * t4;
        float* out_hi = out + (size_t)row_hi * N_DIM + n0 + wn + 2 * t4;
#pragma unroll
        for (int j = 0; j < 8; j++) {
            float2 v;
            v.x = fmaxf(fmaf(acc[i][j][0], inv_lo, bia[j].x), 0.f);
            v.y = fmaxf(fmaf(acc[i][j][1], inv_lo, bia[j].y), 0.f);
            *(float2*)(out_lo + j * 8) = v;
            v.x = fmaxf(fmaf(acc[i][j][2], inv_hi, bia[j].x), 0.f);
            v.y = fmaxf(fmaf(acc[i][j][3], inv_hi, bia[j].y), 0.f);
            *(float2*)(out_hi + j * 8) = v;
        }
    }
}

// ==================== launch ====================
extern "C" void kernel_launch(void* const* d_in, const int* in_sizes, int n_in,
                              void* d_out, int out_size) {
    const float* x = (const float*)d_in[0];
    const float* W = (const float*)d_in[1];
    const float* b = (const float*)d_in[2];
    float* out = (float*)d_out;

    cudaFuncSetAttribute(gemm_kernel, cudaFuncAttributeMaxDynamicSharedMemorySize, SMEM_B);

    prep_kernel<<<B_ROWS + (K_DIM / 32) * (N_DIM / 32), 256>>>(x, W);
    gemm_kernel<<<(B_ROWS / BM) * (N_DIM / BN), 128, SMEM_B>>>(b, out);
}